// round 16
// baseline (speedup 1.0000x reference)
#include <cuda_runtime.h>
#include <cuda_bf16.h>

#define BATCH 8
#define CH    3
#define TT    16
#define H     512
#define WID   512
#define S     224
#define RMAXF 1024.0f

#define PLANES_PER_B (CH * TT)
#define P 3
#define HWPLANE (H * WID)
#define SSPLANE (S * S)
#define PLB  (HWPLANE * 4)         // plane stride, bytes (LDG imm)
#define ROWB (WID * 4)             // source row stride, bytes
#define OPLB (SSPLANE * 4)         // out plane stride, bytes
#define OROWB (S * 4)              // out row stride, bytes

// R14's 2x2-tile / 3-plane shape, with ALL x-selects replaced by tent weights:
// pixel a = m0*u0 + m1*u1 + m2*u2,  u_i = max(0, 1-|fa-i|), fa = sxa-c0 in [0,2)
// pixel b = sum m_i*v_i (4-tap),    v_i = max(0, 1-|fb-i|), fb = sxb-c0 in [0,3)
// Weights computed once per lane-iter, shared by 3 planes x 2 rows. Zero SELs
// in the hot loop. Exact bilinear (zero weights contribute exactly +0.0).
__global__ __launch_bounds__(256, 4) void crop_prompter_kernel(
    const float* __restrict__ x,
    const int*   __restrict__ cam_views,
    const float* __restrict__ resize,
    const float* __restrict__ yoffs,
    const float* __restrict__ xoffs,
    float*       __restrict__ out)
{
    const int group  = blockIdx.z;
    const int plane0 = group * P;
    const int b      = group / (PLANES_PER_B / P);
    const int tx     = threadIdx.x;
    const int ty     = threadIdx.y;

    const int   cam   = __ldg(&cam_views[b]);
    const float r     = floorf(fminf(fmaxf(__ldg(&resize[cam]), (float)H), RMAXF));
    const float scale = (float)H / r;          // in [0.5, 1.0]
    const float yo    = floorf(fminf(fmaxf(__ldg(&yoffs[cam]), 0.0f), r - (float)S));
    const float xo    = floorf(fminf(fmaxf(__ldg(&xoffs[cam]), 0.0f), r - (float)S));

    // Row pair: output rows 2*rp, 2*rp+1
    const int rp = blockIdx.y * 8 + ty;        // 0..111
    const float sy_e = fmaxf((yo + (float)(2 * rp)     + 0.5f) * scale - 0.5f, 0.0f);
    const float sy_o = fmaxf((yo + (float)(2 * rp + 1) + 0.5f) * scale - 0.5f, 0.0f);
    const int   ry   = (int)sy_e;              // <= 254; rows ry..ry+2 valid
    const float fe   = sy_e - (float)ry,  one_fe = 1.0f - fe;
    const float fo   = sy_o - (float)ry;       // in [0,2)
    const float to0  = fmaxf(1.0f - fo, 0.0f);
    const float to1  = 1.0f - fabsf(fo - 1.0f);
    const float to2  = fmaxf(fo - 1.0f, 0.0f);

    const char* __restrict__ pbase =
        (const char*)(x + (size_t)plane0 * HWPLANE + (size_t)ry * WID);
    char* __restrict__ obase =
        (char*)(out + (size_t)plane0 * SSPLANE + (size_t)(2 * rp) * S);

    const float base = (xo + 0.5f) * scale - 0.5f;

    #pragma unroll
    for (int i = 0; i < 4; ++i) {
        const int j = tx + 32 * i;             // col-pair index; pixels 2j,2j+1
        if (j < S / 2) {
            const float rawa = fmaf((float)(2 * j), scale, base);
            const float sxa  = fmaxf(rawa, 0.0f);
            const float sxb  = rawa + scale;   // >= 0.25

            const int   x0a = (int)sxa;
            const int   c0  = x0a & ~1;        // even 8B-aligned window base

            // x tent weights (shared by all planes & both rows)
            const float fa = sxa - (float)c0;  // in [0,2)
            const float u0 = fmaxf(1.0f - fa, 0.0f);
            const float u1 = 1.0f - fabsf(fa - 1.0f);
            const float u2 = fmaxf(fa - 1.0f, 0.0f);

            const float fb = sxb - (float)c0;  // in [0,3)
            const float v0w = fmaxf(1.0f - fb, 0.0f);
            const float v1w = fmaxf(1.0f - fabsf(fb - 1.0f), 0.0f);
            const float v2w = fmaxf(1.0f - fabsf(fb - 2.0f), 0.0f);
            const float v3w = fmaxf(fb - 2.0f, 0.0f);

            const char* a  = pbase + (size_t)c0 * 4;
            char*       oj = obase + (size_t)j * 8;

            // Batched loads: 18 LDG.64 (3 planes x 3 rows x 2)
            float2 L0[P], L1[P], M0[P], M1[P], N0[P], N1[P];
            #pragma unroll
            for (int k = 0; k < P; ++k) {
                L0[k] = *(const float2*)(a + k * PLB);
                L1[k] = *(const float2*)(a + k * PLB + 8);
                M0[k] = *(const float2*)(a + k * PLB + ROWB);
                M1[k] = *(const float2*)(a + k * PLB + ROWB + 8);
                N0[k] = *(const float2*)(a + k * PLB + 2 * ROWB);
                N1[k] = *(const float2*)(a + k * PLB + 2 * ROWB + 8);
            }

            #pragma unroll
            for (int k = 0; k < P; ++k) {
                // even row y-lerp (rows ry, ry+1)
                const float me0 = L0[k].x * one_fe + M0[k].x * fe;
                const float me1 = L0[k].y * one_fe + M0[k].y * fe;
                const float me2 = L1[k].x * one_fe + M1[k].x * fe;
                const float me3 = L1[k].y * one_fe + M1[k].y * fe;

                // odd row y-lerp via tent weights over rows ry..ry+2
                const float mo0 = L0[k].x * to0 + M0[k].x * to1 + N0[k].x * to2;
                const float mo1 = L0[k].y * to0 + M0[k].y * to1 + N0[k].y * to2;
                const float mo2 = L1[k].x * to0 + M1[k].x * to1 + N1[k].x * to2;
                const float mo3 = L1[k].y * to0 + M1[k].y * to1 + N1[k].y * to2;

                // x tents: no selects
                const float va_e = me0 * u0 + me1 * u1 + me2 * u2;
                const float vb_e = me0 * v0w + me1 * v1w + me2 * v2w + me3 * v3w;
                *(float2*)(oj + k * OPLB) = make_float2(va_e, vb_e);

                const float va_o = mo0 * u0 + mo1 * u1 + mo2 * u2;
                const float vb_o = mo0 * v0w + mo1 * v1w + mo2 * v2w + mo3 * v3w;
                *(float2*)(oj + k * OPLB + OROWB) = make_float2(va_o, vb_o);
            }
        }
    }
}

extern "C" void kernel_launch(void* const* d_in, const int* in_sizes, int n_in,
                              void* d_out, int out_size)
{
    const float* x    = (const float*)d_in[0];
    const int*   cams = (const int*)  d_in[1];
    const float* rz   = (const float*)d_in[2];
    const float* yo   = (const float*)d_in[3];
    const float* xo   = (const float*)d_in[4];
    float* out = (float*)d_out;

    dim3 block(32, 8, 1);
    dim3 grid(1, (S / 2) / 8, (BATCH * PLANES_PER_B) / P);
    crop_prompter_kernel<<<grid, block>>>(x, cams, rz, yo, xo, out);
}

// round 17
// speedup vs baseline: 1.0218x; 1.0218x over previous
#include <cuda_runtime.h>
#include <cuda_bf16.h>

#define BATCH 8
#define CH    3
#define TT    16
#define H     512
#define WID   512
#define S     224
#define RMAXF 1024.0f

#define PLANES_PER_B (CH * TT)
#define P 3
#define HWPLANE (H * WID)
#define SSPLANE (S * S)
#define PLB  (HWPLANE * 4)         // plane stride, bytes (LDG imm)
#define ROWB (WID * 4)             // source row stride, bytes
#define OPLB (SSPLANE * 4)         // out plane stride, bytes
#define OROWB (S * 4)              // out row stride, bytes

// 4x2 output tile per lane per iter, 3 planes: window 6 src cols x 3 src rows
// = 9 LDG.64 + 2 STG.128 per plane for 8 pixels. Row sharing via y tent
// weights (R14); column quad via x tent weights off unclamped t_i (exact
// bilinear: each pixel has exactly its 2 taps nonzero, zeros add +0.0).
// 56 quads/row -> 2 iters (second 24/32 lanes active).
__global__ __launch_bounds__(256, 4) void crop_prompter_kernel(
    const float* __restrict__ x,
    const int*   __restrict__ cam_views,
    const float* __restrict__ resize,
    const float* __restrict__ yoffs,
    const float* __restrict__ xoffs,
    float*       __restrict__ out)
{
    const int group  = blockIdx.z;
    const int plane0 = group * P;
    const int b      = group / (PLANES_PER_B / P);
    const int tx     = threadIdx.x;
    const int ty     = threadIdx.y;

    const int   cam   = __ldg(&cam_views[b]);
    const float r     = floorf(fminf(fmaxf(__ldg(&resize[cam]), (float)H), RMAXF));
    const float scale = (float)H / r;          // in [0.5, 1.0]
    const float yo    = floorf(fminf(fmaxf(__ldg(&yoffs[cam]), 0.0f), r - (float)S));
    const float xo    = floorf(fminf(fmaxf(__ldg(&xoffs[cam]), 0.0f), r - (float)S));

    // Row pair: output rows 2*rp, 2*rp+1 (R14 scheme)
    const int rp = blockIdx.y * 8 + ty;        // 0..111
    const float sy_e = fmaxf((yo + (float)(2 * rp)     + 0.5f) * scale - 0.5f, 0.0f);
    const float sy_o = fmaxf((yo + (float)(2 * rp + 1) + 0.5f) * scale - 0.5f, 0.0f);
    const int   ry   = (int)sy_e;              // <= 254; rows ry..ry+2 valid
    const float fe   = sy_e - (float)ry,  one_fe = 1.0f - fe;
    const float fo   = sy_o - (float)ry;       // in [0,2)
    const float to0  = fmaxf(1.0f - fo, 0.0f);
    const float to1  = 1.0f - fabsf(fo - 1.0f);
    const float to2  = fmaxf(fo - 1.0f, 0.0f);

    const char* __restrict__ pbase =
        (const char*)(x + (size_t)plane0 * HWPLANE + (size_t)ry * WID);
    char* __restrict__ obase =
        (char*)(out + (size_t)plane0 * SSPLANE + (size_t)(2 * rp) * S);

    const float base = (xo + 0.5f) * scale - 0.5f;

    #pragma unroll
    for (int i = 0; i < 2; ++i) {
        const int q = tx + 32 * i;             // quad index; pixels 4q..4q+3
        if (q < S / 4) {
            const float raw0 = fmaf((float)(4 * q), scale, base);
            const float sx0  = fmaxf(raw0, 0.0f);
            const int   x00  = (int)sx0;
            const int   c0   = x00 & ~1;       // even 8B-aligned window base

            // unclamped offsets from c0 (exact source coords for px1..3)
            const float tr = raw0 - (float)c0;
            const float t0 = fmaxf(tr, 0.0f);          // == sx0 - c0, [0,2)
            const float t1 = tr + scale;               // [0.25, 3)
            const float t2 = tr + 2.0f * scale;        // [0.75, 4)
            const float t3 = tr + 3.0f * scale;        // [1.25, 5)

            // x tent weights (shared by 3 planes x 2 rows)
            const float w00 = fmaxf(1.0f - t0, 0.0f);
            const float w01 = 1.0f - fabsf(t0 - 1.0f);
            const float w02 = fmaxf(t0 - 1.0f, 0.0f);

            const float w10 = fmaxf(1.0f - t1, 0.0f);
            const float w11 = fmaxf(1.0f - fabsf(t1 - 1.0f), 0.0f);
            const float w12 = fmaxf(1.0f - fabsf(t1 - 2.0f), 0.0f);
            const float w13 = fmaxf(t1 - 2.0f, 0.0f);

            const float w20 = fmaxf(1.0f - t2, 0.0f);
            const float w21 = fmaxf(1.0f - fabsf(t2 - 1.0f), 0.0f);
            const float w22 = fmaxf(1.0f - fabsf(t2 - 2.0f), 0.0f);
            const float w23 = fmaxf(1.0f - fabsf(t2 - 3.0f), 0.0f);
            const float w24 = fmaxf(t2 - 3.0f, 0.0f);

            const float w31 = fmaxf(2.0f - t3, 0.0f);  // t3 >= 1.25
            const float w32 = fmaxf(1.0f - fabsf(t3 - 2.0f), 0.0f);
            const float w33 = fmaxf(1.0f - fabsf(t3 - 3.0f), 0.0f);
            const float w34 = fmaxf(1.0f - fabsf(t3 - 4.0f), 0.0f);
            const float w35 = fmaxf(t3 - 4.0f, 0.0f);

            const char* a  = pbase + (size_t)c0 * 4;
            char*       oj = obase + (size_t)q * 16;

            #pragma unroll
            for (int k = 0; k < P; ++k) {
                // 9 LDG.64: 3 rows x cols c0..c0+5
                const float2 L0 = *(const float2*)(a + k * PLB);
                const float2 L1 = *(const float2*)(a + k * PLB + 8);
                const float2 L2 = *(const float2*)(a + k * PLB + 16);
                const float2 M0 = *(const float2*)(a + k * PLB + ROWB);
                const float2 M1 = *(const float2*)(a + k * PLB + ROWB + 8);
                const float2 M2 = *(const float2*)(a + k * PLB + ROWB + 16);
                const float2 N0 = *(const float2*)(a + k * PLB + 2 * ROWB);
                const float2 N1 = *(const float2*)(a + k * PLB + 2 * ROWB + 8);
                const float2 N2 = *(const float2*)(a + k * PLB + 2 * ROWB + 16);

                // even row y-lerp (6 cols)
                const float me0 = L0.x * one_fe + M0.x * fe;
                const float me1 = L0.y * one_fe + M0.y * fe;
                const float me2 = L1.x * one_fe + M1.x * fe;
                const float me3 = L1.y * one_fe + M1.y * fe;
                const float me4 = L2.x * one_fe + M2.x * fe;
                const float me5 = L2.y * one_fe + M2.y * fe;

                // odd row y tent (6 cols)
                const float mo0 = L0.x * to0 + M0.x * to1 + N0.x * to2;
                const float mo1 = L0.y * to0 + M0.y * to1 + N0.y * to2;
                const float mo2 = L1.x * to0 + M1.x * to1 + N1.x * to2;
                const float mo3 = L1.y * to0 + M1.y * to1 + N1.y * to2;
                const float mo4 = L2.x * to0 + M2.x * to1 + N2.x * to2;
                const float mo5 = L2.y * to0 + M2.y * to1 + N2.y * to2;

                // x tents, even row
                float4 ve;
                ve.x = me0 * w00 + me1 * w01 + me2 * w02;
                ve.y = me0 * w10 + me1 * w11 + me2 * w12 + me3 * w13;
                ve.z = me0 * w20 + me1 * w21 + me2 * w22 + me3 * w23 + me4 * w24;
                ve.w = me1 * w31 + me2 * w32 + me3 * w33 + me4 * w34 + me5 * w35;
                *(float4*)(oj + k * OPLB) = ve;

                // x tents, odd row
                float4 vo;
                vo.x = mo0 * w00 + mo1 * w01 + mo2 * w02;
                vo.y = mo0 * w10 + mo1 * w11 + mo2 * w12 + mo3 * w13;
                vo.z = mo0 * w20 + mo1 * w21 + mo2 * w22 + mo3 * w23 + mo4 * w24;
                vo.w = mo1 * w31 + mo2 * w32 + mo3 * w33 + mo4 * w34 + mo5 * w35;
                *(float4*)(oj + k * OPLB + OROWB) = vo;
            }
        }
    }
}

extern "C" void kernel_launch(void* const* d_in, const int* in_sizes, int n_in,
                              void* d_out, int out_size)
{
    const float* x    = (const float*)d_in[0];
    const int*   cams = (const int*)  d_in[1];
    const float* rz   = (const float*)d_in[2];
    const float* yo   = (const float*)d_in[3];
    const float* xo   = (const float*)d_in[4];
    float* out = (float*)d_out;

    dim3 block(32, 8, 1);
    dim3 grid(1, (S / 2) / 8, (BATCH * PLANES_PER_B) / P);
    crop_prompter_kernel<<<grid, block>>>(x, cams, rz, yo, xo, out);
}